// round 15
// baseline (speedup 1.0000x reference)
#include <cuda_runtime.h>
#include <cuda_fp16.h>
#include <math.h>
#include <stdint.h>

#define Ndim 8192
#define Fdim 128
#define Fo   64
#define Hh   4
#define NCY  64          // Y rows: 64 feats (denominator via register partial sums)
#define BKT  64          // k per tile
#define NTILE (Ndim / BKT)

// ---------------- scratch ----------------
__device__ __align__(16) float  g_Xp[Hh * Ndim * Fo];
__device__ __align__(16) float  g_ss[Hh * Ndim];
__device__ __align__(16) float  g_sn[Hh * Ndim];
__device__ __align__(16) __half g_snh[Hh * Ndim];
__device__ __align__(16) __half g_qh [Hh * Ndim];   // exp(sn - cm)
__device__ __align__(16) __half g_qnh[Hh * Ndim];   // exp(0.2 sn - cm)
__device__ int g_mxi[Hh];                           // monotone-encoded fp32 max
__device__ __align__(16) __half g_Yp[Hh * NCY * Ndim];

// ---------------- helpers ----------------
__device__ __forceinline__ uint32_t smem_u32(const void* p) {
    uint32_t a;
    asm("{ .reg .u64 t; cvta.to.shared.u64 t, %1; cvt.u32.u64 %0, t; }" : "=r"(a) : "l"(p));
    return a;
}
#define SWZ128(x) ((x) ^ (((x) >> 3) & 0x70))

__device__ __forceinline__ void ldsm4(uint32_t* r, uint32_t a) {
    asm volatile("ldmatrix.sync.aligned.m8n8.x4.shared.b16 {%0,%1,%2,%3}, [%4];"
        : "=r"(r[0]), "=r"(r[1]), "=r"(r[2]), "=r"(r[3]) : "r"(a));
}
__device__ __forceinline__ void mma16816(float* d, const uint32_t* a, const uint32_t* b) {
    asm volatile("mma.sync.aligned.m16n8k16.row.col.f32.f16.f16.f32 "
        "{%0,%1,%2,%3}, {%4,%5,%6,%7}, {%8,%9}, {%0,%1,%2,%3};"
        : "+f"(d[0]), "+f"(d[1]), "+f"(d[2]), "+f"(d[3])
        : "r"(a[0]), "r"(a[1]), "r"(a[2]), "r"(a[3]), "r"(b[0]), "r"(b[1]));
}
__device__ __forceinline__ void cp16(uint32_t smaddr, const void* gaddr) {
    asm volatile("cp.async.cg.shared.global [%0], [%1], 16;" :: "r"(smaddr), "l"(gaddr));
}
#define CP_COMMIT() asm volatile("cp.async.commit_group;" ::: "memory")
#define CP_WAIT0()  asm volatile("cp.async.wait_group 0;" ::: "memory")

__device__ __forceinline__ int enc_f32(float f) {
    int i = __float_as_int(f);
    return i >= 0 ? i : (i ^ 0x7fffffff);
}

// ---------------- kernel 1: tiled projection (+ g_mxi init) ----------------
__global__ __launch_bounds__(256)
void proj_kernel(const float* __restrict__ X, const float* __restrict__ W) {
    __shared__ float sX[64][65];
    __shared__ float sW[64][64];
    int t = threadIdx.x;
    int n0 = blockIdx.x * 64, h = blockIdx.y;
    if (blockIdx.x == 0 && blockIdx.y == 0 && t < Hh)
        g_mxi[t] = enc_f32(-1e30f);
    int tc = t & 15, tr = t >> 4;
    float acc[4][4];
#pragma unroll
    for (int r = 0; r < 4; ++r)
#pragma unroll
        for (int c = 0; c < 4; ++c) acc[r][c] = 0.f;

    for (int k0 = 0; k0 < Fdim; k0 += 64) {
        __syncthreads();
#pragma unroll
        for (int r = 0; r < 4; ++r) {
            int idx = t + 256 * r;
            int row = idx >> 4, kq = idx & 15;
            float4 v = __ldg((const float4*)(X + (size_t)(n0 + row) * Fdim + k0) + kq);
            sX[row][kq * 4 + 0] = v.x;
            sX[row][kq * 4 + 1] = v.y;
            sX[row][kq * 4 + 2] = v.z;
            sX[row][kq * 4 + 3] = v.w;
        }
#pragma unroll
        for (int r = 0; r < 4; ++r) {
            int idx = t + 256 * r;
            int row = idx >> 4, kq = idx & 15;
            *(float4*)&sW[row][kq * 4] =
                __ldg((const float4*)(W + ((size_t)(h * Fdim) + k0 + row) * Fo) + kq);
        }
        __syncthreads();
#pragma unroll 16
        for (int kk = 0; kk < 64; ++kk) {
            float4 wv = *(const float4*)&sW[kk][tc * 4];
            float xv0 = sX[tr * 4 + 0][kk];
            float xv1 = sX[tr * 4 + 1][kk];
            float xv2 = sX[tr * 4 + 2][kk];
            float xv3 = sX[tr * 4 + 3][kk];
#define PR(r, xv) \
            acc[r][0] = fmaf(xv, wv.x, acc[r][0]); \
            acc[r][1] = fmaf(xv, wv.y, acc[r][1]); \
            acc[r][2] = fmaf(xv, wv.z, acc[r][2]); \
            acc[r][3] = fmaf(xv, wv.w, acc[r][3]);
            PR(0, xv0) PR(1, xv1) PR(2, xv2) PR(3, xv3)
#undef PR
        }
    }
#pragma unroll
    for (int r = 0; r < 4; ++r) {
        float4 o = make_float4(acc[r][0], acc[r][1], acc[r][2], acc[r][3]);
        *(float4*)(g_Xp + ((size_t)(h * Ndim + n0 + tr * 4 + r)) * Fo + tc * 4) = o;
    }
}

// ---------------- kernel 2: scores + per-head max ----------------
__global__ __launch_bounds__(256)
void score_max_kernel(const float* __restrict__ a_self, const float* __restrict__ a_neigh) {
    __shared__ float red[256];
    int t = threadIdx.x;
    int idx = blockIdx.x * 256 + t;
    int h = idx >> 13;
    const float* xp = g_Xp + (size_t)idx * Fo;
    float s1 = 0.f, s2 = 0.f;
#pragma unroll 16
    for (int d = 0; d < Fo; ++d) {
        float v = xp[d];
        s1 = fmaf(v, __ldg(a_self + h * Fo + d), s1);
        s2 = fmaf(v, __ldg(a_neigh + h * Fo + d), s2);
    }
    g_ss[idx] = s1;
    g_sn[idx] = s2;
    red[t] = s2;
    __syncthreads();
    for (int s = 128; s > 0; s >>= 1) {
        if (t < s) red[t] = fmaxf(red[t], red[t + s]);
        __syncthreads();
    }
    if (t == 0) atomicMax(&g_mxi[h], enc_f32(red[0]));
}

// ---------------- kernel 3: exp tables + fp16 Y operand table ----------------
__global__ __launch_bounds__(256)
void pqy_kernel() {
    __shared__ float sXp[64][65];
    int t = threadIdx.x;
    int m0 = blockIdx.x * 64, h = blockIdx.y;

    if (t < 64) {
        int idx = h * Ndim + m0 + t;
        int k = g_mxi[h];
        float mx = __int_as_float(k >= 0 ? k : (k ^ 0x7fffffff));
        float cm = mx > 0.f ? mx : 0.2f * mx;
        float sn = g_sn[idx];
        g_qh [idx] = __float2half_rn(expf(sn - cm));
        g_qnh[idx] = __float2half_rn(expf(0.2f * sn - cm));
        g_snh[idx] = __float2half_rn(sn);
    }

#pragma unroll
    for (int r = 0; r < 4; ++r) {
        int idx = t + 256 * r;
        int j = idx >> 4, dq = idx & 15;
        float4 v = __ldg((const float4*)(g_Xp + ((size_t)(h * Ndim + m0 + j)) * Fo) + dq);
        sXp[j][dq * 4 + 0] = v.x;
        sXp[j][dq * 4 + 1] = v.y;
        sXp[j][dq * 4 + 2] = v.z;
        sXp[j][dq * 4 + 3] = v.w;
    }
    __syncthreads();

    for (int idx = t; idx < NCY * 8; idx += 256) {
        int row = idx >> 3, g8 = idx & 7;
        ushort u[8];
#pragma unroll
        for (int p = 0; p < 8; ++p) {
            int m = g8 * 8 + p;
            u[p] = __half_as_ushort(__float2half_rn(sXp[m][row]));
        }
        uint4 pk;
        pk.x = (uint32_t)u[0] | ((uint32_t)u[1] << 16);
        pk.y = (uint32_t)u[2] | ((uint32_t)u[3] << 16);
        pk.z = (uint32_t)u[4] | ((uint32_t)u[5] << 16);
        pk.w = (uint32_t)u[6] | ((uint32_t)u[7] << 16);
        *(uint4*)(g_Yp + ((size_t)(h * NCY + row)) * Ndim + m0 + g8 * 8) = pk;
    }
}

// ---------------- main kernel ----------------
// smem: stage[buf] @ buf*24576: S_W=0 (16KB), S_Y=16384 (8KB)
#define S_W    0
#define S_Y    16384
#define STAGE  24576
#define SMEM_DYN (1024 + 2 * STAGE)

__global__ __launch_bounds__(256, 2)
void gat_mma(const float* __restrict__ A, float* __restrict__ out) {
    extern __shared__ char dsm[];
    uint32_t sb0 = smem_u32(dsm);
    uint32_t sb = (sb0 + 1023u) & ~1023u;
    char* smp = dsm + (sb - sb0);

    int t = threadIdx.x, wid = t >> 5, lane = t & 31;
    int h = blockIdx.y, n0 = blockIdx.x * 128;

    // weight-gen mapping: q = 8-col group (t&7), rows i0 + 32r (i0 = t>>3, r<4)
    int q  = t & 7;
    int i0 = t >> 3;
    __half2 ssh[4], Rh[4];
    uint32_t offs[4];
#pragma unroll
    for (int r = 0; r < 4; ++r) {
        int gi = h * Ndim + n0 + i0 + 32 * r;
        float ss = g_ss[gi];
        ssh[r] = __float2half2_rn(ss);
        Rh[r]  = __float2half2_rn(fminf(expf(-0.8f * ss), 60000.f));
        offs[r] = SWZ128((uint32_t)((i0 + 32 * r) * 128 + q * 16));
    }
    const __half2 hz = __float2half2_rn(0.f);
    const float4* A4 = (const float4*)A;
    const __half* snh = g_snh + h * Ndim;
    const __half* qhp = g_qh  + h * Ndim;
    const __half* qnp = g_qnh + h * Ndim;

    float dsum[4];
#pragma unroll
    for (int r = 0; r < 4; ++r) dsum[r] = 0.f;

    // mma: 4x2 warp grid: rg (32 rows = 2 row-tiles), cg (4 n-tiles = 32 cols)
    int rg = wid & 3, cg = wid >> 2;
    uint32_t aRow  = (uint32_t)(rg * 32 + (lane & 15)) * 128 + ((lane >> 4) ? 16u : 0u);
    uint32_t bRow4 = (uint32_t)(lane & 7) * 128 + (((lane >> 3) & 1) ? 16u : 0u)
                   + (uint32_t)(lane >> 4) * 1024 + (uint32_t)cg * 4096;

    float acc[2][4][4];
#pragma unroll
    for (int rt = 0; rt < 2; ++rt)
#pragma unroll
        for (int nt = 0; nt < 4; ++nt)
#pragma unroll
            for (int c = 0; c < 4; ++c) acc[rt][nt][c] = 0.f;

    // wgen: 4 rows x 8 cols, STS.128, fp16 partial row-sums into fp32 dsum
#define WGEN(stoff, m0v)                                                            \
    {                                                                               \
        uint4 snp = *(const uint4*)(snh + (m0v) + q * 8);                           \
        uint4 qp  = *(const uint4*)(qhp + (m0v) + q * 8);                           \
        uint4 qqp = *(const uint4*)(qnp + (m0v) + q * 8);                           \
        __half2 sn[4] = {*(__half2*)&snp.x, *(__half2*)&snp.y, *(__half2*)&snp.z, *(__half2*)&snp.w}; \
        __half2 qv[4] = {*(__half2*)&qp.x,  *(__half2*)&qp.y,  *(__half2*)&qp.z,  *(__half2*)&qp.w};  \
        __half2 qn[4] = {*(__half2*)&qqp.x, *(__half2*)&qqp.y, *(__half2*)&qqp.z, *(__half2*)&qqp.w}; \
        _Pragma("unroll")                                                           \
        for (int r = 0; r < 4; ++r) {                                               \
            __half2 a0 = __floats2half2_rn(av0[r].x, av0[r].y);                     \
            __half2 a1 = __floats2half2_rn(av0[r].z, av0[r].w);                     \
            __half2 a2 = __floats2half2_rn(av1[r].x, av1[r].y);                     \
            __half2 a3 = __floats2half2_rn(av1[r].z, av1[r].w);                     \
            __half2 w0, w1, w2, w3;                                                 \
            {                                                                       \
                __half2 g = __hgt2(__hadd2(ssh[r], sn[0]), hz);                     \
                __half2 rn = __hmul2(Rh[r], qn[0]);                                 \
                w0 = __hmul2(a0, __hfma2(g, __hsub2(qv[0], rn), rn));               \
            }                                                                       \
            {                                                                       \
                __half2 g = __hgt2(__hadd2(ssh[r], sn[1]), hz);                     \
                __half2 rn = __hmul2(Rh[r], qn[1]);                                 \
                w1 = __hmul2(a1, __hfma2(g, __hsub2(qv[1], rn), rn));               \
            }                                                                       \
            {                                                                       \
                __half2 g = __hgt2(__hadd2(ssh[r], sn[2]), hz);                     \
                __half2 rn = __hmul2(Rh[r], qn[2]);                                 \
                w2 = __hmul2(a2, __hfma2(g, __hsub2(qv[2], rn), rn));               \
            }                                                                       \
            {                                                                       \
                __half2 g = __hgt2(__hadd2(ssh[r], sn[3]), hz);                     \
                __half2 rn = __hmul2(Rh[r], qn[3]);                                 \
                w3 = __hmul2(a3, __hfma2(g, __hsub2(qv[3], rn), rn));               \
            }                                                                       \
            __half2 ps = __hadd2(__hadd2(w0, w1), __hadd2(w2, w3));                 \
            float2 pf = __half22float2(ps);                                         \
            dsum[r] += pf.x + pf.y;                                                 \
            uint4 pk = make_uint4(*(uint32_t*)&w0, *(uint32_t*)&w1,                 \
                                  *(uint32_t*)&w2, *(uint32_t*)&w3);                \
            *(uint4*)(smp + (stoff) + offs[r]) = pk;                                \
        }                                                                           \
    }

    // ---- prologue: stage 0 ----
    {
        for (int idx = t; idx < NCY * 8; idx += 256) {
            int row = idx >> 3, kq = idx & 7;
            cp16(sb + S_Y + SWZ128((uint32_t)(row * 128 + kq * 16)),
                 g_Yp + ((size_t)(h * NCY + row)) * Ndim + kq * 8);
        }
        CP_COMMIT();
        float4 av0[4], av1[4];
#pragma unroll
        for (int r = 0; r < 4; ++r) {
            size_t base = (size_t)(n0 + i0 + 32 * r) * (Ndim / 4) + q * 2;
            av0[r] = __ldg(A4 + base);
            av1[r] = __ldg(A4 + base + 1);
        }
        WGEN(S_W, 0)
        CP_WAIT0();
        __syncthreads();
    }

    // ---- main loop ----
    for (int tile = 0; tile < NTILE; ++tile) {
        int cur = tile & 1;
        uint32_t stc = (uint32_t)cur * STAGE;
        uint32_t stn = (uint32_t)(cur ^ 1) * STAGE;
        int m1 = (tile + 1) * BKT;

        float4 av0[4], av1[4];
        if (tile < NTILE - 1) {
            for (int idx = t; idx < NCY * 8; idx += 256) {
                int row = idx >> 3, kq = idx & 7;
                cp16(sb + stn + S_Y + SWZ128((uint32_t)(row * 128 + kq * 16)),
                     g_Yp + ((size_t)(h * NCY + row)) * Ndim + m1 + kq * 8);
            }
            CP_COMMIT();
#pragma unroll
            for (int r = 0; r < 4; ++r) {
                size_t base = (size_t)(n0 + i0 + 32 * r) * (Ndim / 4) + (m1 >> 2) + q * 2;
                av0[r] = __ldg(A4 + base);
                av1[r] = __ldg(A4 + base + 1);
            }
        }

        // ---- mma on current stage ----
        uint32_t wbase = sb + stc + S_W;
        uint32_t ybase = sb + stc + S_Y;
#pragma unroll
        for (int ks = 0; ks < 4; ++ks) {
            uint32_t a0[4], a1[4];
            ldsm4(a0, wbase + SWZ128(aRow + ks * 32));
            ldsm4(a1, wbase + SWZ128(aRow + 2048 + ks * 32));
#pragma unroll
            for (int np = 0; np < 2; ++np) {
                uint32_t b4[4];
                ldsm4(b4, ybase + SWZ128(bRow4 + (uint32_t)np * 2048 + ks * 32));
                mma16816(acc[0][np * 2 + 0], a0, b4);
                mma16816(acc[1][np * 2 + 0], a1, b4);
                mma16816(acc[0][np * 2 + 1], a0, b4 + 2);
                mma16816(acc[1][np * 2 + 1], a1, b4 + 2);
            }
        }

        // ---- generate next W tile ----
        if (tile < NTILE - 1) {
            WGEN(stn + S_W, m1)
            CP_WAIT0();
        }
        __syncthreads();
    }
#undef WGEN

    // ---- denominator: reduce dsum over the 8 q-lanes ----
    float* sDen = (float*)smp;   // stage 0 W area is free (last mma read stage 1)
#pragma unroll
    for (int r = 0; r < 4; ++r) {
        float v = dsum[r];
        v += __shfl_xor_sync(0xffffffffu, v, 1);
        v += __shfl_xor_sync(0xffffffffu, v, 2);
        v += __shfl_xor_sync(0xffffffffu, v, 4);
        if (q == 0) sDen[i0 + 32 * r] = v;
    }
    __syncthreads();

    // ---- register epilogue ----
    int r0 = rg * 32 + (lane >> 2);
    float inv0 = 1.0f / sDen[r0];        // row-tile 0, sub-row 0
    float inv1 = 1.0f / sDen[r0 + 8];    // row-tile 0, sub-row 1
    float inv2 = 1.0f / sDen[r0 + 16];   // row-tile 1, sub-row 0
    float inv3 = 1.0f / sDen[r0 + 24];   // row-tile 1, sub-row 1
    float* op = out + (size_t)(n0 + r0) * (Hh * Fo) + h * Fo + cg * 32;
    const size_t rstride = (size_t)8 * (Hh * Fo);
#pragma unroll
    for (int nt = 0; nt < 4; ++nt) {
        int c = nt * 8 + (lane & 3) * 2;
        float2 v0 = make_float2(fmaxf(acc[0][nt][0] * inv0, 0.f), fmaxf(acc[0][nt][1] * inv0, 0.f));
        float2 v1 = make_float2(fmaxf(acc[0][nt][2] * inv1, 0.f), fmaxf(acc[0][nt][3] * inv1, 0.f));
        float2 v2 = make_float2(fmaxf(acc[1][nt][0] * inv2, 0.f), fmaxf(acc[1][nt][1] * inv2, 0.f));
        float2 v3 = make_float2(fmaxf(acc[1][nt][2] * inv3, 0.f), fmaxf(acc[1][nt][3] * inv3, 0.f));
        *(float2*)(op + c) = v0;
        *(float2*)(op + rstride + c) = v1;
        *(float2*)(op + 2 * rstride + c) = v2;
        *(float2*)(op + 3 * rstride + c) = v3;
    }
}

// ---------------- launcher ----------------
extern "C" void kernel_launch(void* const* d_in, const int* in_sizes, int n_in,
                              void* d_out, int out_size) {
    const float* X       = (const float*)d_in[0];
    const float* A       = (const float*)d_in[1];
    const float* W       = (const float*)d_in[2];
    const float* a_self  = (const float*)d_in[3];
    const float* a_neigh = (const float*)d_in[4];
    float* out = (float*)d_out;

    cudaFuncSetAttribute(gat_mma, cudaFuncAttributeMaxDynamicSharedMemorySize, SMEM_DYN);

    proj_kernel     <<<dim3(Ndim / 64, Hh), 256>>>(X, W);
    score_max_kernel<<<(Hh * Ndim) / 256, 256>>>(a_self, a_neigh);
    pqy_kernel      <<<dim3(Ndim / 64, Hh), 256>>>();
    gat_mma         <<<dim3(Ndim / 128, Hh), 256, SMEM_DYN>>>(A, out);
}

// round 16
// speedup vs baseline: 1.0419x; 1.0419x over previous
#include <cuda_runtime.h>
#include <cuda_fp16.h>
#include <math.h>
#include <stdint.h>

#define Ndim 8192
#define Fdim 128
#define Fo   64
#define Hh   4
#define NC   72          // Y rows: 64 feats + 1 ones(denom) + 7 pad
#define BKT  64          // k per tile
#define NTILE (Ndim / BKT)

// ---------------- scratch ----------------
__device__ __align__(16) float  g_Xp[Hh * Ndim * Fo];
__device__ __align__(16) float  g_ss[Hh * Ndim];
__device__ __align__(16) float  g_sn[Hh * Ndim];
__device__ __align__(16) __half g_snh[Hh * Ndim];
__device__ __align__(16) __half g_qh [Hh * Ndim];   // exp(sn - cm)
__device__ __align__(16) __half g_qnh[Hh * Ndim];   // exp(0.2 sn - cm)
__device__ int g_mxi[Hh];                           // monotone-encoded fp32 max
__device__ __align__(16) __half g_Yp[Hh * NC * Ndim];

// ---------------- helpers ----------------
__device__ __forceinline__ uint32_t smem_u32(const void* p) {
    uint32_t a;
    asm("{ .reg .u64 t; cvta.to.shared.u64 t, %1; cvt.u32.u64 %0, t; }" : "=r"(a) : "l"(p));
    return a;
}
#define SWZ128(x) ((x) ^ (((x) >> 3) & 0x70))

__device__ __forceinline__ void ldsm4(uint32_t* r, uint32_t a) {
    asm volatile("ldmatrix.sync.aligned.m8n8.x4.shared.b16 {%0,%1,%2,%3}, [%4];"
        : "=r"(r[0]), "=r"(r[1]), "=r"(r[2]), "=r"(r[3]) : "r"(a));
}
__device__ __forceinline__ void ldsm2(uint32_t* r, uint32_t a) {
    asm volatile("ldmatrix.sync.aligned.m8n8.x2.shared.b16 {%0,%1}, [%2];"
        : "=r"(r[0]), "=r"(r[1]) : "r"(a));
}
__device__ __forceinline__ void mma16816(float* d, const uint32_t* a, const uint32_t* b) {
    asm volatile("mma.sync.aligned.m16n8k16.row.col.f32.f16.f16.f32 "
        "{%0,%1,%2,%3}, {%4,%5,%6,%7}, {%8,%9}, {%0,%1,%2,%3};"
        : "+f"(d[0]), "+f"(d[1]), "+f"(d[2]), "+f"(d[3])
        : "r"(a[0]), "r"(a[1]), "r"(a[2]), "r"(a[3]), "r"(b[0]), "r"(b[1]));
}
__device__ __forceinline__ void cp16(uint32_t smaddr, const void* gaddr) {
    asm volatile("cp.async.cg.shared.global [%0], [%1], 16;" :: "r"(smaddr), "l"(gaddr));
}
#define CP_COMMIT() asm volatile("cp.async.commit_group;" ::: "memory")
#define CP_WAIT0()  asm volatile("cp.async.wait_group 0;" ::: "memory")

__device__ __forceinline__ int enc_f32(float f) {
    int i = __float_as_int(f);
    return i >= 0 ? i : (i ^ 0x7fffffff);
}

// ---------------- kernel 1: tiled projection (+ g_mxi init) ----------------
__global__ __launch_bounds__(256)
void proj_kernel(const float* __restrict__ X, const float* __restrict__ W) {
    __shared__ float sX[64][65];
    __shared__ float sW[64][64];
    int t = threadIdx.x;
    int n0 = blockIdx.x * 64, h = blockIdx.y;
    if (blockIdx.x == 0 && blockIdx.y == 0 && t < Hh)
        g_mxi[t] = enc_f32(-1e30f);
    int tc = t & 15, tr = t >> 4;
    float acc[4][4];
#pragma unroll
    for (int r = 0; r < 4; ++r)
#pragma unroll
        for (int c = 0; c < 4; ++c) acc[r][c] = 0.f;

    for (int k0 = 0; k0 < Fdim; k0 += 64) {
        __syncthreads();
#pragma unroll
        for (int r = 0; r < 4; ++r) {
            int idx = t + 256 * r;
            int row = idx >> 4, kq = idx & 15;
            float4 v = __ldg((const float4*)(X + (size_t)(n0 + row) * Fdim + k0) + kq);
            sX[row][kq * 4 + 0] = v.x;
            sX[row][kq * 4 + 1] = v.y;
            sX[row][kq * 4 + 2] = v.z;
            sX[row][kq * 4 + 3] = v.w;
        }
#pragma unroll
        for (int r = 0; r < 4; ++r) {
            int idx = t + 256 * r;
            int row = idx >> 4, kq = idx & 15;
            *(float4*)&sW[row][kq * 4] =
                __ldg((const float4*)(W + ((size_t)(h * Fdim) + k0 + row) * Fo) + kq);
        }
        __syncthreads();
#pragma unroll 16
        for (int kk = 0; kk < 64; ++kk) {
            float4 wv = *(const float4*)&sW[kk][tc * 4];
            float xv0 = sX[tr * 4 + 0][kk];
            float xv1 = sX[tr * 4 + 1][kk];
            float xv2 = sX[tr * 4 + 2][kk];
            float xv3 = sX[tr * 4 + 3][kk];
#define PR(r, xv) \
            acc[r][0] = fmaf(xv, wv.x, acc[r][0]); \
            acc[r][1] = fmaf(xv, wv.y, acc[r][1]); \
            acc[r][2] = fmaf(xv, wv.z, acc[r][2]); \
            acc[r][3] = fmaf(xv, wv.w, acc[r][3]);
            PR(0, xv0) PR(1, xv1) PR(2, xv2) PR(3, xv3)
#undef PR
        }
    }
#pragma unroll
    for (int r = 0; r < 4; ++r) {
        float4 o = make_float4(acc[r][0], acc[r][1], acc[r][2], acc[r][3]);
        *(float4*)(g_Xp + ((size_t)(h * Ndim + n0 + tr * 4 + r)) * Fo + tc * 4) = o;
    }
}

// ---------------- kernel 2: scores + per-head max ----------------
__global__ __launch_bounds__(256)
void score_max_kernel(const float* __restrict__ a_self, const float* __restrict__ a_neigh) {
    __shared__ float red[256];
    int t = threadIdx.x;
    int idx = blockIdx.x * 256 + t;
    int h = idx >> 13;
    const float* xp = g_Xp + (size_t)idx * Fo;
    float s1 = 0.f, s2 = 0.f;
#pragma unroll 16
    for (int d = 0; d < Fo; ++d) {
        float v = xp[d];
        s1 = fmaf(v, __ldg(a_self + h * Fo + d), s1);
        s2 = fmaf(v, __ldg(a_neigh + h * Fo + d), s2);
    }
    g_ss[idx] = s1;
    g_sn[idx] = s2;
    red[t] = s2;
    __syncthreads();
    for (int s = 128; s > 0; s >>= 1) {
        if (t < s) red[t] = fmaxf(red[t], red[t + s]);
        __syncthreads();
    }
    if (t == 0) atomicMax(&g_mxi[h], enc_f32(red[0]));
}

// ---------------- kernel 3: exp tables + fp16 Y operand table ----------------
__global__ __launch_bounds__(256)
void pqy_kernel() {
    __shared__ float sXp[64][65];
    int t = threadIdx.x;
    int m0 = blockIdx.x * 64, h = blockIdx.y;

    if (t < 64) {
        int idx = h * Ndim + m0 + t;
        int k = g_mxi[h];
        float mx = __int_as_float(k >= 0 ? k : (k ^ 0x7fffffff));
        float cm = mx > 0.f ? mx : 0.2f * mx;
        float sn = g_sn[idx];
        g_qh [idx] = __float2half_rn(expf(sn - cm));
        g_qnh[idx] = __float2half_rn(expf(0.2f * sn - cm));
        g_snh[idx] = __float2half_rn(sn);
    }

#pragma unroll
    for (int r = 0; r < 4; ++r) {
        int idx = t + 256 * r;
        int j = idx >> 4, dq = idx & 15;
        float4 v = __ldg((const float4*)(g_Xp + ((size_t)(h * Ndim + m0 + j)) * Fo) + dq);
        sXp[j][dq * 4 + 0] = v.x;
        sXp[j][dq * 4 + 1] = v.y;
        sXp[j][dq * 4 + 2] = v.z;
        sXp[j][dq * 4 + 3] = v.w;
    }
    __syncthreads();

    for (int idx = t; idx < NC * 8; idx += 256) {
        int row = idx >> 3, g8 = idx & 7;
        ushort u[8];
#pragma unroll
        for (int p = 0; p < 8; ++p) {
            int m = g8 * 8 + p;
            float v = (row < 64) ? sXp[m][row] : (row == 64 ? 1.f : 0.f);
            u[p] = __half_as_ushort(__float2half_rn(v));
        }
        uint4 pk;
        pk.x = (uint32_t)u[0] | ((uint32_t)u[1] << 16);
        pk.y = (uint32_t)u[2] | ((uint32_t)u[3] << 16);
        pk.z = (uint32_t)u[4] | ((uint32_t)u[5] << 16);
        pk.w = (uint32_t)u[6] | ((uint32_t)u[7] << 16);
        *(uint4*)(g_Yp + ((size_t)(h * NC + row)) * Ndim + m0 + g8 * 8) = pk;
    }
}

// ---------------- main kernel: 64-row CTAs, 4/SM ----------------
// smem: stage[buf] @ buf*17408: S_W=0 (8KB, 64 rows), S_Y=8192 (9216B, 72 rows)
#define S_W    0
#define S_Y    8192
#define STAGE  17408
#define SMEM_DYN (1024 + 2 * STAGE)
#define NTHR   128

__global__ __launch_bounds__(NTHR, 4)
void gat_mma(const float* __restrict__ A, float* __restrict__ out) {
    extern __shared__ char dsm[];
    uint32_t sb0 = smem_u32(dsm);
    uint32_t sb = (sb0 + 1023u) & ~1023u;
    char* smp = dsm + (sb - sb0);

    int t = threadIdx.x, wid = t >> 5, lane = t & 31;
    int h = blockIdx.y, n0 = blockIdx.x * 64;

    // weight-gen mapping: q = float4-col (t&15), rows i0 + 8r (i0 = t>>4 in 0..7)
    int q  = t & 15;
    int i0 = t >> 4;
    __half2 ssh[8], Rh[8];
    uint32_t offs[8];
#pragma unroll
    for (int r = 0; r < 8; ++r) {
        int gi = h * Ndim + n0 + i0 + 8 * r;
        float ss = g_ss[gi];
        ssh[r] = __float2half2_rn(ss);
        Rh[r]  = __float2half2_rn(fminf(expf(-0.8f * ss), 60000.f));
        offs[r] = SWZ128((uint32_t)((i0 + 8 * r) * 128 + q * 8));
    }
    const __half2 hz = __float2half2_rn(0.f);
    const float4* A4 = (const float4*)A;
    const __half* snh = g_snh + h * Ndim;
    const __half* qh  = g_qh  + h * Ndim;
    const __half* qnh = g_qnh + h * Ndim;

    // mma: warp owns rows wid*16..+15, all 9 n-tiles
    uint32_t aRow  = (uint32_t)(wid * 16 + (lane & 15)) * 128 + ((lane >> 4) ? 16u : 0u);
    uint32_t bRow  = (uint32_t)(lane & 7) * 128 + (((lane >> 3) & 1) ? 16u : 0u);
    uint32_t bRow4 = bRow + (uint32_t)(lane >> 4) * 1024;

    float acc[9][4];
#pragma unroll
    for (int nt = 0; nt < 9; ++nt)
#pragma unroll
        for (int c = 0; c < 4; ++c) acc[nt][c] = 0.f;

    // P-cancelled weight-gen: w = A * (t>0 ? Q : R*Qn)
#define WGEN(stoff, m0v)                                                            \
    {                                                                               \
        uint2 snp = *(const uint2*)(snh + (m0v) + q * 4);                           \
        uint2 qp  = *(const uint2*)(qh  + (m0v) + q * 4);                           \
        uint2 qnp = *(const uint2*)(qnh + (m0v) + q * 4);                           \
        __half2 sn01 = *(__half2*)&snp.x, sn23 = *(__half2*)&snp.y;                 \
        __half2 q01  = *(__half2*)&qp.x,  q23  = *(__half2*)&qp.y;                  \
        __half2 qn01 = *(__half2*)&qnp.x, qn23 = *(__half2*)&qnp.y;                 \
        _Pragma("unroll")                                                           \
        for (int r = 0; r < 8; ++r) {                                               \
            __half2 a01 = __floats2half2_rn(av[r].x, av[r].y);                      \
            __half2 a23 = __floats2half2_rn(av[r].z, av[r].w);                      \
            __half2 g01 = __hgt2(__hadd2(ssh[r], sn01), hz);                        \
            __half2 g23 = __hgt2(__hadd2(ssh[r], sn23), hz);                        \
            __half2 rn01 = __hmul2(Rh[r], qn01);                                    \
            __half2 rn23 = __hmul2(Rh[r], qn23);                                    \
            __half2 s01 = __hfma2(g01, __hsub2(q01, rn01), rn01);                   \
            __half2 s23 = __hfma2(g23, __hsub2(q23, rn23), rn23);                   \
            __half2 w01 = __hmul2(a01, s01);                                        \
            __half2 w23 = __hmul2(a23, s23);                                        \
            *(uint2*)(smp + (stoff) + offs[r]) = make_uint2(*(uint32_t*)&w01, *(uint32_t*)&w23); \
        }                                                                           \
    }

    // ---- prologue: stage 0 ----
    {
        for (int idx = t; idx < NC * 8; idx += NTHR) {
            int row = idx >> 3, kq = idx & 7;
            cp16(sb + S_Y + SWZ128((uint32_t)(row * 128 + kq * 16)),
                 g_Yp + ((size_t)(h * NC + row)) * Ndim + kq * 8);
        }
        CP_COMMIT();
        float4 av[8];
#pragma unroll
        for (int r = 0; r < 8; ++r)
            av[r] = __ldg(A4 + (size_t)(n0 + i0 + 8 * r) * (Ndim / 4) + q);
        WGEN(S_W, 0)
        CP_WAIT0();
        __syncthreads();
    }

    // ---- main loop ----
    for (int tile = 0; tile < NTILE; ++tile) {
        int cur = tile & 1;
        uint32_t stc = (uint32_t)cur * STAGE;
        uint32_t stn = (uint32_t)(cur ^ 1) * STAGE;
        int m1 = (tile + 1) * BKT;

        float4 av[8];
        if (tile < NTILE - 1) {
            for (int idx = t; idx < NC * 8; idx += NTHR) {
                int row = idx >> 3, kq = idx & 7;
                cp16(sb + stn + S_Y + SWZ128((uint32_t)(row * 128 + kq * 16)),
                     g_Yp + ((size_t)(h * NC + row)) * Ndim + m1 + kq * 8);
            }
            CP_COMMIT();
#pragma unroll
            for (int r = 0; r < 8; ++r)
                av[r] = __ldg(A4 + (size_t)(n0 + i0 + 8 * r) * (Ndim / 4) + (m1 >> 2) + q);
        }

        // ---- mma on current stage ----
        uint32_t wbase = sb + stc + S_W;
        uint32_t ybase = sb + stc + S_Y;
#pragma unroll
        for (int ks = 0; ks < 4; ++ks) {
            uint32_t a4[4];
            ldsm4(a4, wbase + SWZ128(aRow + ks * 32));
#pragma unroll
            for (int np = 0; np < 4; ++np) {
                uint32_t b4[4];
                ldsm4(b4, ybase + SWZ128(bRow4 + (uint32_t)np * 2048 + ks * 32));
                mma16816(acc[np * 2 + 0], a4, b4);
                mma16816(acc[np * 2 + 1], a4, b4 + 2);
            }
            {
                uint32_t b2[2];
                ldsm2(b2, ybase + SWZ128(bRow + 8192u + ks * 32));
                mma16816(acc[8], a4, b2);
            }
        }

        // ---- generate next W tile ----
        if (tile < NTILE - 1) {
            WGEN(stn + S_W, m1)
            CP_WAIT0();
        }
        __syncthreads();
    }
#undef WGEN

    // ---- register epilogue: den from ones column (col 64 of n-tile 8) ----
    float den0 = __shfl_sync(0xffffffffu, acc[8][0], lane & 28);
    float den1 = __shfl_sync(0xffffffffu, acc[8][2], lane & 28);
    float inv0 = 1.0f / den0;
    float inv1 = 1.0f / den1;
    int rowg = n0 + wid * 16 + (lane >> 2);
    float* op0 = out + (size_t)rowg * (Hh * Fo) + h * Fo;
    float* op1 = op0 + (size_t)8 * (Hh * Fo);
#pragma unroll
    for (int nt = 0; nt < 8; ++nt) {
        int c = nt * 8 + (lane & 3) * 2;
        float2 v0 = make_float2(fmaxf(acc[nt][0] * inv0, 0.f), fmaxf(acc[nt][1] * inv0, 0.f));
        float2 v1 = make_float2(fmaxf(acc[nt][2] * inv1, 0.f), fmaxf(acc[nt][3] * inv1, 0.f));
        *(float2*)(op0 + c) = v0;
        *(float2*)(op1 + c) = v1;
    }
}

// ---------------- launcher ----------------
extern "C" void kernel_launch(void* const* d_in, const int* in_sizes, int n_in,
                              void* d_out, int out_size) {
    const float* X       = (const float*)d_in[0];
    const float* A       = (const float*)d_in[1];
    const float* W       = (const float*)d_in[2];
    const float* a_self  = (const float*)d_in[3];
    const float* a_neigh = (const float*)d_in[4];
    float* out = (float*)d_out;

    cudaFuncSetAttribute(gat_mma, cudaFuncAttributeMaxDynamicSharedMemorySize, SMEM_DYN);

    proj_kernel     <<<dim3(Ndim / 64, Hh), 256>>>(X, W);
    score_max_kernel<<<(Hh * Ndim) / 256, 256>>>(a_self, a_neigh);
    pqy_kernel      <<<dim3(Ndim / 64, Hh), 256>>>();
    gat_mma         <<<dim3(Ndim / 64, Hh), NTHR, SMEM_DYN>>>(A, out);
}